// round 14
// baseline (speedup 1.0000x reference)
#include <cuda_runtime.h>

// RC timing on 200k independent 16-pin trees — mode-per-thread, geometry
// dedup, coalesced IO; sweep scratch W doubles as the store-transpose buffer.
//
// Block = 192 threads = 6 warps = 2 net-groups x 3 modes; lane = net.
// fa_local[i] in [0,i) => single-sweep bottom-up / top-down recurrences in a
// per-warp scratch W with layout [slot][lane], slot stride 35 floats:
//   - sweep accesses (fixed slot, all lanes): banks (3*slot+lane)%32 -> CF
//   - transposed store reads (pin-major): banks 12(lane&3)+(lane>>2)+C -> CF
// so every metric materializes in W for free and is stored with
// 16 LDS.32 + 4 coalesced STG.128 (32 L1-cyc) instead of the 48-cyc
// STS/LDS/STG staging round-trip. Metric 0's store shares the load-sweep
// seed. Inputs still come through swizzled staging (ld16w).
//
// Output: out[(metric*3 + mode)*nPins + pin].

#define NS       16
#define TPB      192
#define NETS_PB  64
#define WS       35                     // W slot stride (floats)

__device__ __forceinline__ int swz(int n, int k) {
    return 4 * n + ((k + n + (n >> 1)) & 3);
}

// Warp-coalesced load of 16 floats/thread (thread n = lane owns chunk 4n..4n+3).
__device__ __forceinline__ void ld16w(float4* St, const float4* wb, int lane,
                                      bool full, bool act, float* dst)
{
    if (full) {
        float4 t0 = __ldg(wb + lane),      t1 = __ldg(wb + 32 + lane),
               t2 = __ldg(wb + 64 + lane), t3 = __ldg(wb + 96 + lane);
        St[swz(lane >> 2, lane & 3)] = t0;
        { int c = 32 + lane; St[swz(c >> 2, c & 3)] = t1; }
        { int c = 64 + lane; St[swz(c >> 2, c & 3)] = t2; }
        { int c = 96 + lane; St[swz(c >> 2, c & 3)] = t3; }
        __syncwarp();
#pragma unroll
        for (int k = 0; k < 4; k++) {
            float4 v = St[swz(lane, k)];
            dst[4*k] = v.x; dst[4*k+1] = v.y; dst[4*k+2] = v.z; dst[4*k+3] = v.w;
        }
    } else if (act) {
#pragma unroll
        for (int k = 0; k < 4; k++) {
            float4 v = __ldg(wb + 4 * lane + k);
            dst[4*k] = v.x; dst[4*k+1] = v.y; dst[4*k+2] = v.z; dst[4*k+3] = v.w;
        }
    } else {
#pragma unroll
        for (int i = 0; i < NS; i++) dst[i] = 0.0f;
    }
}

// Store one metric tile: transposed read from warp's W region + coalesced STG.
// Fallback (partial warp): scattered per-thread stores from register array.
__device__ __forceinline__ void stW(const float* Wb, float4* wb, int lane,
                                    bool full, bool act, const float* regs)
{
    if (full) {
        __syncwarp();
#pragma unroll
        for (int j = 0; j < 4; j++) {
            int c   = j * 32 + lane;
            int net = c >> 2;
            int pb  = (c & 3) * 4;
            float4 vv = make_float4(Wb[(pb + 0) * WS + net],
                                    Wb[(pb + 1) * WS + net],
                                    Wb[(pb + 2) * WS + net],
                                    Wb[(pb + 3) * WS + net]);
            __stcs(wb + c, vv);
        }
        __syncwarp();
    } else if (act) {
#pragma unroll
        for (int k = 0; k < 4; k++)
            __stcs(wb + 4 * lane + k,
                   make_float4(regs[4*k], regs[4*k+1], regs[4*k+2], regs[4*k+3]));
    }
}

__global__ void __launch_bounds__(TPB, 4)
rct_kernel(const float* __restrict__ x, const float* __restrict__ y,
           const int* __restrict__ fa,
           const float* __restrict__ c0, const float* __restrict__ c1,
           const float* __restrict__ c2,
           float* __restrict__ out, int nNets, int nPins)
{
    __shared__ float4 Stg[6 * 2 * 128];  // per-warp ping-pong staging, 24 KB
    __shared__ float  Wsm[6 * NS * WS];  // per-warp sweep scratch, 13.4 KB
    __shared__ float  RNsm[2 * 1024];    // per-group (x,y)->(res,nc) fl2, 8 KB
    __shared__ int2   Fsm[2 * 32];       // per-group packed parent nibbles

    const int wib  = threadIdx.x >> 5;   // 0..5
    const int lane = threadIdx.x & 31;
    const int mode = wib % 3;
    const int grp  = wib / 3;            // 0..1
    const int netbase = blockIdx.x * NETS_PB + grp * 32;
    const int t    = netbase + lane;     // net id
    const bool act = (t < nNets);
    const bool full = (netbase + 32 <= nNets);  // warp-uniform
    const int g    = t * NS;

    float4* S0 = Stg + wib * 256;               // two 128-float4 buffers
    float*  Wb = Wsm  + wib * (NS * WS);        // warp W base
    float*  W  = Wb + lane;                     // my column
    float*  RN = RNsm + grp * 1024 + lane * 2;  // float2 column
    int2*   F2 = Fsm  + grp * 32 + lane;

    int   foff[NS];                      // parent slot * WS (element offset)
    float res[NS];
    float ncr[NS];
    int   ph = 0;

    // ---- geometry (mode-0 warps): res, nc, parents once per net -----------
    if (mode == 0) {
        int fl[NS];
        {
            float flf[NS];
            ld16w(S0 + (ph++ & 1) * 128, (const float4*)fa + (size_t)netbase * 4,
                  lane, full, act, flf);
            unsigned pk0 = 0, pk1 = 0;
#pragma unroll
            for (int i = 0; i < NS; i++) {
                fl[i] = act ? (__float_as_int(flf[i]) - g) : 0;
                foff[i] = fl[i] * WS;
                if (i < 8) pk0 |= (unsigned)fl[i] << (i * 4);
                else       pk1 |= (unsigned)fl[i] << ((i - 8) * 4);
            }
            *F2 = make_int2((int)pk0, (int)pk1);
        }
        float xr[NS], yr[NS];
        ld16w(S0 + (ph++ & 1) * 128, (const float4*)x + (size_t)netbase * 4,
              lane, full, act, xr);
        ld16w(S0 + (ph++ & 1) * 128, (const float4*)y + (size_t)netbase * 4,
              lane, full, act, yr);
#pragma unroll
        for (int i = 0; i < NS; i++)
            *(float2*)(RN + i * 64) = make_float2(xr[i], yr[i]);
        res[0] = 0.0f;
#pragma unroll
        for (int i = 1; i < NS; i++) {
            float2 p = *(const float2*)(RN + fl[i] * 64 * 2 / 2);  // fl*64 fl2
            res[i] = (fabsf(xr[i] - p.x) + fabsf(yr[i] - p.y)) * 5.0e-5f;
        }
        // wire caps: scatter half-edge caps up one level (own W region)
        W[0] = 0.0f;
#pragma unroll
        for (int i = 1; i < NS; i++) W[i * WS] = res[i];
#pragma unroll
        for (int i = NS - 1; i >= 1; i--) W[foff[i]] += res[i];
#pragma unroll
        for (int i = 0; i < NS; i++) {
            ncr[i] = W[i * WS];
            *(float2*)(RN + i * 64) = make_float2(res[i], ncr[i]);
        }
    }

    __syncthreads();

    if (mode != 0) {
        int2 pk = *F2;
        unsigned pk0 = (unsigned)pk.x, pk1 = (unsigned)pk.y;
#pragma unroll
        for (int i = 0; i < 8; i++)  foff[i] = (int)((pk0 >> (i * 4)) & 15u) * WS;
#pragma unroll
        for (int i = 8; i < NS; i++) foff[i] = (int)((pk1 >> ((i - 8) * 4)) & 15u) * WS;
#pragma unroll
        for (int i = 0; i < NS; i++) {
            float2 rn = *(const float2*)(RN + i * 64);
            res[i] = rn.x; ncr[i] = rn.y;
        }
    }

    const float* cb = (mode == 0) ? c0 : ((mode == 1) ? c1 : c2);

    // ---- pin caps (metric 0): pc = base cap + wire cap --------------------
    float u[NS], v[NS];          // u: pc -> ldelay -> beta ; v: load -> delay
    {
        float cr[NS];
        ld16w(S0 + (ph++ & 1) * 128, (const float4*)cb + (size_t)netbase * 4,
              lane, full, act, cr);
#pragma unroll
        for (int i = 0; i < NS; i++) u[i] = cr[i] + ncr[i];
    }

#define OB(metric) ((float4*)out + (size_t)((metric) * 3 + mode) * (nPins >> 2) \
                    + (size_t)netbase * 4)

    // seed W with pc (doubles as metric-0 tile AND load-sweep seed)
#pragma unroll
    for (int i = 0; i < NS; i++) W[i * WS] = u[i];
    stW(Wb, OB(0), lane, full, act, u);

    // ---- load: bottom-up subtree sum of pin_cap (RMW in place) ------------
#pragma unroll
    for (int i = NS - 1; i >= 1; i--) {
        v[i] = W[i * WS];                                // descendants done
        W[foff[i]] += v[i];
    }
    v[0] = W[0];
    stW(Wb, OB(1), lane, full, act, v);

    // ---- delay: top-down path sum; v: load -> delay -----------------------
    W[0] = 0.0f;
    v[0] = 0.0f;
#pragma unroll
    for (int i = 1; i < NS; i++) {
        float pd = W[foff[i]];                           // parent = delay
        float d  = fmaf(res[i], v[i], pd);
        W[i * WS] = d;
        v[i] = d;
    }
    stW(Wb, OB(2), lane, full, act, v);

    // ---- ldelay: bottom-up subtree sum of pc*delay; u: pc -> ldelay -------
#pragma unroll
    for (int i = 0; i < NS; i++) W[i * WS] = u[i] * v[i];
#pragma unroll
    for (int i = NS - 1; i >= 1; i--) {
        u[i] = W[i * WS];
        W[foff[i]] += u[i];
    }
    u[0] = W[0];
    stW(Wb, OB(3), lane, full, act, u);

    // ---- beta: top-down path sum; u: ldelay -> beta -----------------------
    W[0] = 0.0f;
    u[0] = 0.0f;
#pragma unroll
    for (int i = 1; i < NS; i++) {
        float pb = W[foff[i]];
        float b  = fmaf(res[i], u[i], pb);
        W[i * WS] = b;
        u[i] = b;
    }
    stW(Wb, OB(4), lane, full, act, u);

    // ---- impulse = sqrt(max(2*beta - delay^2, 1e-12)) ---------------------
    {
        float im[NS];
        im[0] = 1.0e-6f;
        W[0] = 1.0e-6f;
#pragma unroll
        for (int i = 1; i < NS; i++) {
            float q2 = fmaf(-v[i], v[i], u[i] + u[i]);
            q2 = fmaxf(q2, 1.0e-12f);
            im[i] = q2 * rsqrtf(q2);                     // sqrt via MUFU.RSQ
            W[i * WS] = im[i];
        }
        stW(Wb, OB(5), lane, full, act, im);
    }
#undef OB
}

extern "C" void kernel_launch(void* const* d_in, const int* in_sizes, int n_in,
                              void* d_out, int out_size)
{
    const float* x  = (const float*)d_in[0];
    const float* y  = (const float*)d_in[1];
    const int*   fa = (const int*)  d_in[4];
    const float* c0 = (const float*)d_in[8];
    const float* c1 = (const float*)d_in[9];
    const float* c2 = (const float*)d_in[10];

    const int nPins = in_sizes[0];
    const int nNets = in_sizes[3] - 1;   // net_flat_topo_sort_start has nNets+1

    const int grid = (nNets + NETS_PB - 1) / NETS_PB;
    rct_kernel<<<grid, TPB>>>(x, y, fa, c0, c1, c2, (float*)d_out, nNets, nPins);
}

// round 15
// speedup vs baseline: 1.0004x; 1.0004x over previous
#include <cuda_runtime.h>

// RC timing on 200k independent 16-pin trees — mode-per-thread, block-level
// geometry dedup, coalesced IO via swizzled SINGLE-buffer staging (R11
// structure, smaller smem footprint -> 6 blocks/SM instead of 4).
//
// Block = 192 threads = 6 warps = 2 net-groups x 3 modes; lane = net.
// fa_local[i] in [0,i) => single-sweep bottom-up / top-down recurrences via
// lane-transposed shared scratch [slot][lane] (bank == lane, no conflicts).
// Mode-0 warps compute geometry (res, wire caps, parents) once per net and
// publish through shared; modes 1/2 consume after one __syncthreads.
// All global IO goes through a per-warp 2KB staging buffer with swizzle
//   P(n,k) = 4n + ((k + n + (n>>1)) & 3)
// (conflict-free in both thread-major and lane-major float4 phases);
// __syncwarp guards buffer reuse (warp-local latency only).
//
// Output: out[(metric*3 + mode)*nPins + pin].

#define NS       16
#define TPB      192
#define NETS_PB  64

__device__ __forceinline__ int swz(int n, int k) {
    return 4 * n + ((k + n + (n >> 1)) & 3);
}

// Warp-coalesced load of 16 floats/thread (thread n = lane owns chunk 4n..4n+3).
__device__ __forceinline__ void ld16w(float4* St, const float4* wb, int lane,
                                      bool full, bool act, float* dst)
{
    if (full) {
        float4 t0 = __ldg(wb + lane),      t1 = __ldg(wb + 32 + lane),
               t2 = __ldg(wb + 64 + lane), t3 = __ldg(wb + 96 + lane);
        __syncwarp();                    // prior reads of St complete
        St[swz(lane >> 2, lane & 3)] = t0;
        { int c = 32 + lane; St[swz(c >> 2, c & 3)] = t1; }
        { int c = 64 + lane; St[swz(c >> 2, c & 3)] = t2; }
        { int c = 96 + lane; St[swz(c >> 2, c & 3)] = t3; }
        __syncwarp();
#pragma unroll
        for (int k = 0; k < 4; k++) {
            float4 v = St[swz(lane, k)];
            dst[4*k] = v.x; dst[4*k+1] = v.y; dst[4*k+2] = v.z; dst[4*k+3] = v.w;
        }
    } else if (act) {
#pragma unroll
        for (int k = 0; k < 4; k++) {
            float4 v = __ldg(wb + 4 * lane + k);
            dst[4*k] = v.x; dst[4*k+1] = v.y; dst[4*k+2] = v.z; dst[4*k+3] = v.w;
        }
    } else {
#pragma unroll
        for (int i = 0; i < NS; i++) dst[i] = 0.0f;
    }
}

// Warp-coalesced store of 16 floats/thread.
__device__ __forceinline__ void st16w(float4* St, float4* wb, int lane,
                                      bool full, bool act, const float* a)
{
    if (full) {
        __syncwarp();                    // prior reads of St complete
#pragma unroll
        for (int k = 0; k < 4; k++)
            St[swz(lane, k)] = make_float4(a[4*k], a[4*k+1], a[4*k+2], a[4*k+3]);
        __syncwarp();
#pragma unroll
        for (int j = 0; j < 4; j++) {
            int c = j * 32 + lane;
            __stcs(wb + c, St[swz(c >> 2, c & 3)]);
        }
    } else if (act) {
#pragma unroll
        for (int k = 0; k < 4; k++)
            __stcs(wb + 4 * lane + k,
                   make_float4(a[4*k], a[4*k+1], a[4*k+2], a[4*k+3]));
    }
}

__global__ void __launch_bounds__(TPB, 6)
rct_kernel(const float* __restrict__ x, const float* __restrict__ y,
           const int* __restrict__ fa,
           const float* __restrict__ c0, const float* __restrict__ c1,
           const float* __restrict__ c2,
           float* __restrict__ out, int nNets, int nPins)
{
    __shared__ float4 Stg[6 * 128];      // per-warp single staging, 12 KB
    __shared__ float  Wsm[6 * 512];      // per-warp sweep scratch, 12 KB
    __shared__ float  RNsm[2 * 1024];    // per-group (x,y)->(res,nc) fl2, 8 KB
    __shared__ int2   Fsm[2 * 32];       // per-group packed parent nibbles

    const int wib  = threadIdx.x >> 5;   // 0..5
    const int lane = threadIdx.x & 31;
    const int mode = wib % 3;
    const int grp  = wib / 3;            // 0..1
    const int netbase = blockIdx.x * NETS_PB + grp * 32;
    const int t    = netbase + lane;     // net id
    const bool act = (t < nNets);
    const bool full = (netbase + 32 <= nNets);  // warp-uniform
    const int g    = t * NS;

    float4* S0 = Stg + wib * 128;               // one 2KB buffer per warp
    float*  W  = Wsm  + wib * 512 + lane;       // [slot][lane] column
    float*  RN = RNsm + grp * 1024 + lane * 2;  // float2 column
    int2*   F2 = Fsm  + grp * 32 + lane;

    int   foff[NS];                      // parent slot * 32 (element offset)
    float res[NS];
    float ncr[NS];

    // ---- geometry (mode-0 warps): res, nc, parents once per net -----------
    if (mode == 0) {
        {
            float flf[NS];
            ld16w(S0, (const float4*)fa + (size_t)netbase * 4,
                  lane, full, act, flf);
            unsigned pk0 = 0, pk1 = 0;
#pragma unroll
            for (int i = 0; i < NS; i++) {
                int s = act ? (__float_as_int(flf[i]) - g) : 0;
                foff[i] = s * 32;
                if (i < 8) pk0 |= (unsigned)s << (i * 4);
                else       pk1 |= (unsigned)s << ((i - 8) * 4);
            }
            *F2 = make_int2((int)pk0, (int)pk1);
        }
        float xr[NS], yr[NS];
        ld16w(S0, (const float4*)x + (size_t)netbase * 4, lane, full, act, xr);
        ld16w(S0, (const float4*)y + (size_t)netbase * 4, lane, full, act, yr);
#pragma unroll
        for (int i = 0; i < NS; i++)
            *(float2*)(RN + i * 64) = make_float2(xr[i], yr[i]);
        res[0] = 0.0f;
#pragma unroll
        for (int i = 1; i < NS; i++) {
            float2 p = *(const float2*)(RN + foff[i] * 2);
            res[i] = (fabsf(xr[i] - p.x) + fabsf(yr[i] - p.y)) * 5.0e-5f;
        }
        // wire caps: scatter half-edge caps up one level (own W region)
        W[0] = 0.0f;
#pragma unroll
        for (int i = 1; i < NS; i++) W[i * 32] = res[i];
#pragma unroll
        for (int i = NS - 1; i >= 1; i--) W[foff[i]] += res[i];
        // capture nc in regs while publishing (res, nc) for modes 1/2
#pragma unroll
        for (int i = 0; i < NS; i++) {
            ncr[i] = W[i * 32];
            *(float2*)(RN + i * 64) = make_float2(res[i], ncr[i]);
        }
    }

    __syncthreads();

    if (mode != 0) {
        int2 pk = *F2;
        unsigned pk0 = (unsigned)pk.x, pk1 = (unsigned)pk.y;
#pragma unroll
        for (int i = 0; i < 8; i++)  foff[i] = (int)((pk0 >> (i * 4)) & 15u) * 32;
#pragma unroll
        for (int i = 8; i < NS; i++) foff[i] = (int)((pk1 >> ((i - 8) * 4)) & 15u) * 32;
#pragma unroll
        for (int i = 0; i < NS; i++) {
            float2 rn = *(const float2*)(RN + i * 64);
            res[i] = rn.x; ncr[i] = rn.y;
        }
    }

    const float* cb = (mode == 0) ? c0 : ((mode == 1) ? c1 : c2);
#define OB(metric) ((float4*)out + (size_t)((metric) * 3 + mode) * (nPins >> 2) \
                    + (size_t)netbase * 4)

    // ---- pin caps (metric 0) ----------------------------------------------
    float u[NS], v[NS];          // u: pc -> ldelay -> beta ; v: load -> delay
    {
        float cr[NS];
        ld16w(S0, (const float4*)cb + (size_t)netbase * 4, lane, full, act, cr);
#pragma unroll
        for (int i = 0; i < NS; i++) u[i] = cr[i] + ncr[i];
    }
    st16w(S0, OB(0), lane, full, act, u);

    // ---- load: bottom-up subtree sum of pin_cap ---------------------------
#pragma unroll
    for (int i = 0; i < NS - 1; i++) W[i * 32] = u[i];   // slot 15 stays in reg
    v[NS - 1] = u[NS - 1];
    W[foff[NS - 1]] += v[NS - 1];
#pragma unroll
    for (int i = NS - 2; i >= 1; i--) {
        v[i] = W[i * 32];                                // descendants done
        W[foff[i]] += v[i];
    }
    v[0] = W[0];
    st16w(S0, OB(1), lane, full, act, v);

    // ---- delay: top-down path sum; v: load -> delay -----------------------
    W[0] = 0.0f;
    v[0] = 0.0f;                                         // root delay = 0
#pragma unroll
    for (int i = 1; i < NS; i++) {
        float pd = W[foff[i]];                           // parent = delay
        float d  = fmaf(res[i], v[i], pd);
        if (i < NS - 1) W[i * 32] = d;                   // 15 never a parent
        v[i] = d;
    }
    st16w(S0, OB(2), lane, full, act, v);

    // ---- ldelay: bottom-up subtree sum of pc*delay; u: pc -> ldelay -------
#pragma unroll
    for (int i = 0; i < NS - 1; i++) W[i * 32] = u[i] * v[i];
    u[NS - 1] = u[NS - 1] * v[NS - 1];
    W[foff[NS - 1]] += u[NS - 1];
#pragma unroll
    for (int i = NS - 2; i >= 1; i--) {
        u[i] = W[i * 32];
        W[foff[i]] += u[i];
    }
    u[0] = W[0];
    st16w(S0, OB(3), lane, full, act, u);

    // ---- beta: top-down path sum; u: ldelay -> beta -----------------------
    W[0] = 0.0f;
    u[0] = 0.0f;                                         // root beta = 0
#pragma unroll
    for (int i = 1; i < NS; i++) {
        float pb = W[foff[i]];
        float b  = fmaf(res[i], u[i], pb);
        if (i < NS - 1) W[i * 32] = b;
        u[i] = b;
    }
    st16w(S0, OB(4), lane, full, act, u);

    // ---- impulse = sqrt(max(2*beta - delay^2, 1e-12)) ---------------------
    {
        float im[NS];
        im[0] = 1.0e-6f;
#pragma unroll
        for (int i = 1; i < NS; i++) {
            float q2 = fmaf(-v[i], v[i], u[i] + u[i]);
            q2 = fmaxf(q2, 1.0e-12f);
            im[i] = q2 * rsqrtf(q2);                     // sqrt via MUFU.RSQ
        }
        st16w(S0, OB(5), lane, full, act, im);
    }
#undef OB
}

extern "C" void kernel_launch(void* const* d_in, const int* in_sizes, int n_in,
                              void* d_out, int out_size)
{
    const float* x  = (const float*)d_in[0];
    const float* y  = (const float*)d_in[1];
    const int*   fa = (const int*)  d_in[4];
    const float* c0 = (const float*)d_in[8];
    const float* c1 = (const float*)d_in[9];
    const float* c2 = (const float*)d_in[10];

    const int nPins = in_sizes[0];
    const int nNets = in_sizes[3] - 1;   // net_flat_topo_sort_start has nNets+1

    const int grid = (nNets + NETS_PB - 1) / NETS_PB;
    rct_kernel<<<grid, TPB>>>(x, y, fa, c0, c1, c2, (float*)d_out, nNets, nPins);
}

// round 16
// speedup vs baseline: 1.0567x; 1.0563x over previous
#include <cuda_runtime.h>

// RC timing on 200k independent 16-pin trees — R11 structure (mode-per-thread,
// geometry dedup, swizzled ping-pong input staging) + stores served directly
// from the sweep scratch W with slot stride 34 (conflict-free transpose).
//
// W layout [slot][lane], slot stride WS=34 floats:
//   sweep access (fixed slot, lanes 0..31): banks (2*slot + lane) % 32  -> CF
//   transposed store read (k,j fixed):      banks 8(lane&3)+(lane>>2)+2k+8j -> CF
// Every metric materializes in W during its sweep, so a store is
// 16 LDS.32 + 4 coalesced STG.128 (32 wf) instead of the 48-wf staged
// STS/LDS/STG round-trip. (R14 tried this with stride 35 — 12*(lane&3)
// aliasing made every transposed read 2-way conflicted; 34 fixes it.)
//
// Output: out[(metric*3 + mode)*nPins + pin].

#define NS       16
#define TPB      192
#define NETS_PB  64
#define WS       34                     // W slot stride (floats)

__device__ __forceinline__ int swz(int n, int k) {
    return 4 * n + ((k + n + (n >> 1)) & 3);
}

// Warp-coalesced load of 16 floats/thread (thread n = lane owns chunk 4n..4n+3).
__device__ __forceinline__ void ld16w(float4* St, const float4* wb, int lane,
                                      bool full, bool act, float* dst)
{
    if (full) {
        float4 t0 = __ldg(wb + lane),      t1 = __ldg(wb + 32 + lane),
               t2 = __ldg(wb + 64 + lane), t3 = __ldg(wb + 96 + lane);
        St[swz(lane >> 2, lane & 3)] = t0;
        { int c = 32 + lane; St[swz(c >> 2, c & 3)] = t1; }
        { int c = 64 + lane; St[swz(c >> 2, c & 3)] = t2; }
        { int c = 96 + lane; St[swz(c >> 2, c & 3)] = t3; }
        __syncwarp();
#pragma unroll
        for (int k = 0; k < 4; k++) {
            float4 v = St[swz(lane, k)];
            dst[4*k] = v.x; dst[4*k+1] = v.y; dst[4*k+2] = v.z; dst[4*k+3] = v.w;
        }
    } else if (act) {
#pragma unroll
        for (int k = 0; k < 4; k++) {
            float4 v = __ldg(wb + 4 * lane + k);
            dst[4*k] = v.x; dst[4*k+1] = v.y; dst[4*k+2] = v.z; dst[4*k+3] = v.w;
        }
    } else {
#pragma unroll
        for (int i = 0; i < NS; i++) dst[i] = 0.0f;
    }
}

// Store one metric tile straight out of the warp's W region (CF transpose).
// Fallback (partial warp): scattered per-thread stores from register array.
__device__ __forceinline__ void stW(const float* Wb, float4* wb, int lane,
                                    bool full, bool act, const float* regs)
{
    if (full) {
        __syncwarp();                    // all columns of W written
#pragma unroll
        for (int j = 0; j < 4; j++) {
            const int c   = j * 32 + lane;
            const int net = (j << 3) + (lane >> 2);
            const int pb  = (lane & 3) << 2;
            float4 vv = make_float4(Wb[(pb + 0) * WS + net],
                                    Wb[(pb + 1) * WS + net],
                                    Wb[(pb + 2) * WS + net],
                                    Wb[(pb + 3) * WS + net]);
            __stcs(wb + c, vv);
        }
        __syncwarp();                    // W free for reuse
    } else if (act) {
#pragma unroll
        for (int k = 0; k < 4; k++)
            __stcs(wb + 4 * lane + k,
                   make_float4(regs[4*k], regs[4*k+1], regs[4*k+2], regs[4*k+3]));
    }
}

__global__ void __launch_bounds__(TPB, 4)
rct_kernel(const float* __restrict__ x, const float* __restrict__ y,
           const int* __restrict__ fa,
           const float* __restrict__ c0, const float* __restrict__ c1,
           const float* __restrict__ c2,
           float* __restrict__ out, int nNets, int nPins)
{
    __shared__ float4 Stg[6 * 2 * 128];  // per-warp ping-pong input staging, 24 KB
    __shared__ float  Wsm[6 * NS * WS];  // per-warp sweep scratch, 12.75 KB
    __shared__ float  RNsm[2 * 1024];    // per-group (x,y)->(res,nc) fl2, 8 KB
    __shared__ int2   Fsm[2 * 32];       // per-group packed parent nibbles

    const int wib  = threadIdx.x >> 5;   // 0..5
    const int lane = threadIdx.x & 31;
    const int mode = wib % 3;
    const int grp  = wib / 3;            // 0..1
    const int netbase = blockIdx.x * NETS_PB + grp * 32;
    const int t    = netbase + lane;     // net id
    const bool act = (t < nNets);
    const bool full = (netbase + 32 <= nNets);  // warp-uniform
    const int g    = t * NS;

    float4* S0 = Stg + wib * 256;               // two 2KB buffers
    float*  Wb = Wsm  + wib * (NS * WS);        // warp W base
    float*  W  = Wb + lane;                     // my column
    float*  RN = RNsm + grp * 1024 + lane * 2;  // float2 column
    int2*   F2 = Fsm  + grp * 32 + lane;

    int   foff[NS];                      // parent slot * WS (element offset)
    float res[NS];
    float ncr[NS];
    int   ph = 0;                        // staging ping-pong phase

    // ---- geometry (mode-0 warps): res, nc, parents once per net -----------
    if (mode == 0) {
        int fl[NS];
        {
            float flf[NS];
            ld16w(S0 + (ph++ & 1) * 128, (const float4*)fa + (size_t)netbase * 4,
                  lane, full, act, flf);
            unsigned pk0 = 0, pk1 = 0;
#pragma unroll
            for (int i = 0; i < NS; i++) {
                fl[i] = act ? (__float_as_int(flf[i]) - g) : 0;
                foff[i] = fl[i] * WS;
                if (i < 8) pk0 |= (unsigned)fl[i] << (i * 4);
                else       pk1 |= (unsigned)fl[i] << ((i - 8) * 4);
            }
            *F2 = make_int2((int)pk0, (int)pk1);
        }
        float xr[NS], yr[NS];
        ld16w(S0 + (ph++ & 1) * 128, (const float4*)x + (size_t)netbase * 4,
              lane, full, act, xr);
        ld16w(S0 + (ph++ & 1) * 128, (const float4*)y + (size_t)netbase * 4,
              lane, full, act, yr);
#pragma unroll
        for (int i = 0; i < NS; i++)
            *(float2*)(RN + i * 64) = make_float2(xr[i], yr[i]);
        res[0] = 0.0f;
#pragma unroll
        for (int i = 1; i < NS; i++) {
            float2 p = *(const float2*)(RN + fl[i] * 64);
            res[i] = (fabsf(xr[i] - p.x) + fabsf(yr[i] - p.y)) * 5.0e-5f;
        }
        // wire caps: scatter half-edge caps up one level (own W region)
        W[0] = 0.0f;
#pragma unroll
        for (int i = 1; i < NS; i++) W[i * WS] = res[i];
#pragma unroll
        for (int i = NS - 1; i >= 1; i--) W[foff[i]] += res[i];
        // capture nc in regs while publishing (res, nc) for modes 1/2
#pragma unroll
        for (int i = 0; i < NS; i++) {
            ncr[i] = W[i * WS];
            *(float2*)(RN + i * 64) = make_float2(res[i], ncr[i]);
        }
    }

    __syncthreads();

    if (mode != 0) {
        int2 pk = *F2;
        unsigned pk0 = (unsigned)pk.x, pk1 = (unsigned)pk.y;
#pragma unroll
        for (int i = 0; i < 8; i++)  foff[i] = (int)((pk0 >> (i * 4)) & 15u) * WS;
#pragma unroll
        for (int i = 8; i < NS; i++) foff[i] = (int)((pk1 >> ((i - 8) * 4)) & 15u) * WS;
#pragma unroll
        for (int i = 0; i < NS; i++) {
            float2 rn = *(const float2*)(RN + i * 64);
            res[i] = rn.x; ncr[i] = rn.y;
        }
    }

    const float* cb = (mode == 0) ? c0 : ((mode == 1) ? c1 : c2);
#define OB(metric) ((float4*)out + (size_t)((metric) * 3 + mode) * (nPins >> 2) \
                    + (size_t)netbase * 4)

    // ---- pin caps (metric 0): pc = base cap + wire cap --------------------
    float u[NS], v[NS];          // u: pc -> ldelay -> beta ; v: load -> delay
    {
        float cr[NS];
        ld16w(S0 + (ph++ & 1) * 128, (const float4*)cb + (size_t)netbase * 4,
              lane, full, act, cr);
#pragma unroll
        for (int i = 0; i < NS; i++) u[i] = cr[i] + ncr[i];
    }

    // seed W with pc: doubles as the metric-0 tile AND the load-sweep seed
#pragma unroll
    for (int i = 0; i < NS; i++) W[i * WS] = u[i];
    stW(Wb, OB(0), lane, full, act, u);

    // ---- load: bottom-up subtree sum of pin_cap (in place in W) -----------
#pragma unroll
    for (int i = NS - 1; i >= 1; i--) {
        v[i] = W[i * WS];                                // descendants done
        W[foff[i]] += v[i];
    }
    v[0] = W[0];
    stW(Wb, OB(1), lane, full, act, v);

    // ---- delay: top-down path sum; v: load -> delay -----------------------
    W[0] = 0.0f;
    v[0] = 0.0f;                                         // root delay = 0
#pragma unroll
    for (int i = 1; i < NS; i++) {
        float pd = W[foff[i]];                           // parent = delay
        float d  = fmaf(res[i], v[i], pd);
        W[i * WS] = d;
        v[i] = d;
    }
    stW(Wb, OB(2), lane, full, act, v);

    // ---- ldelay: bottom-up subtree sum of pc*delay; u: pc -> ldelay -------
#pragma unroll
    for (int i = 0; i < NS; i++) W[i * WS] = u[i] * v[i];
#pragma unroll
    for (int i = NS - 1; i >= 1; i--) {
        u[i] = W[i * WS];
        W[foff[i]] += u[i];
    }
    u[0] = W[0];
    stW(Wb, OB(3), lane, full, act, u);

    // ---- beta: top-down path sum; u: ldelay -> beta -----------------------
    W[0] = 0.0f;
    u[0] = 0.0f;                                         // root beta = 0
#pragma unroll
    for (int i = 1; i < NS; i++) {
        float pb = W[foff[i]];
        float b  = fmaf(res[i], u[i], pb);
        W[i * WS] = b;
        u[i] = b;
    }
    stW(Wb, OB(4), lane, full, act, u);

    // ---- impulse = sqrt(max(2*beta - delay^2, 1e-12)) ---------------------
    {
        float im[NS];
        im[0] = 1.0e-6f;
        W[0] = 1.0e-6f;
#pragma unroll
        for (int i = 1; i < NS; i++) {
            float q2 = fmaf(-v[i], v[i], u[i] + u[i]);
            q2 = fmaxf(q2, 1.0e-12f);
            im[i] = q2 * rsqrtf(q2);                     // sqrt via MUFU.RSQ
            W[i * WS] = im[i];
        }
        stW(Wb, OB(5), lane, full, act, im);
    }
#undef OB
}

extern "C" void kernel_launch(void* const* d_in, const int* in_sizes, int n_in,
                              void* d_out, int out_size)
{
    const float* x  = (const float*)d_in[0];
    const float* y  = (const float*)d_in[1];
    const int*   fa = (const int*)  d_in[4];
    const float* c0 = (const float*)d_in[8];
    const float* c1 = (const float*)d_in[9];
    const float* c2 = (const float*)d_in[10];

    const int nPins = in_sizes[0];
    const int nNets = in_sizes[3] - 1;   // net_flat_topo_sort_start has nNets+1

    const int grid = (nNets + NETS_PB - 1) / NETS_PB;
    rct_kernel<<<grid, TPB>>>(x, y, fa, c0, c1, c2, (float*)d_out, nNets, nPins);
}